// round 9
// baseline (speedup 1.0000x reference)
#include <cuda_runtime.h>
#include <cuda_fp16.h>
#include <mma.h>
#include <math.h>
#include <stdint.h>

using namespace nvcuda;

// Problem constants: N=100000, F=256, UNITS=256, DIM=128
#define F_DIM   256
#define UNITS   256
#define DIM     128
#define N_MAX   100000
#define M_TILE  64
#define THREADS 256
#define LDA     264          // A smem leading dim (halfs), 528B stride
#define LDB     24           // B smem leading dim (halfs), 48B stride
#define LDC     260          // C smem leading dim (floats), 1040B stride
#define KC      16           // K chunk per pipeline stage
#define NCHUNK  (F_DIM / KC) // 16
#define NBUF    3            // pipeline depth

// Scratch
__device__ __half g_xh[(size_t)N_MAX * UNITS];   // packed [mean|var] fp16, ~51 MB
__device__ int    g_rowptr[N_MAX + 1];
__device__ float  g_kl;
__device__ __half g_Wh[UNITS * F_DIM];           // W^T hi fp16, [n][k]
__device__ __half g_Wl[UNITS * F_DIM];           // W^T lo fp16, [n][k]

// ---------------------------------------------------------------------------
// MUFU-free exp (x <= 0) and elu
// ---------------------------------------------------------------------------
__device__ __forceinline__ float fast_exp(float x) {
    x = fmaxf(x, -80.f);
    const float t = x * 1.4426950408889634f;
    const float nf = rintf(t);
    const float f = t - nf;
    float p = 1.5253232e-5f;
    p = fmaf(p, f, 1.54035304e-4f);
    p = fmaf(p, f, 1.33335581e-3f);
    p = fmaf(p, f, 9.61812911e-3f);
    p = fmaf(p, f, 5.55041087e-2f);
    p = fmaf(p, f, 2.40226507e-1f);
    p = fmaf(p, f, 6.93147181e-1f);
    p = fmaf(p, f, 1.0f);
    return __int_as_float(__float_as_int(p) + (((int)nf) << 23));
}
__device__ __forceinline__ float elu_f(float x) {
    if (x > 0.f) return x;
    if (x > -0.5f) {
        float p = 1.98412698e-4f;
        p = fmaf(p, x, 1.38888889e-3f);
        p = fmaf(p, x, 8.33333333e-3f);
        p = fmaf(p, x, 4.16666667e-2f);
        p = fmaf(p, x, 1.66666667e-1f);
        p = fmaf(p, x, 0.5f);
        p = fmaf(p, x, 1.0f);
        return x * p;
    }
    return fast_exp(x) - 1.0f;
}

__device__ __forceinline__ uint32_t smem_u32(const void* p) {
    uint32_t a;
    asm("{ .reg .u64 t; cvta.to.shared.u64 t, %1; cvt.u32.u64 %0, t; }"
        : "=r"(a) : "l"(p));
    return a;
}
__device__ __forceinline__ void cp_async16(uint32_t dst, const void* src) {
    asm volatile("cp.async.cg.shared.global [%0], [%1], 16;"
                 :: "r"(dst), "l"(src) : "memory");
}
#define CP_COMMIT()  asm volatile("cp.async.commit_group;" ::: "memory")
#define CP_WAIT(n)   asm volatile("cp.async.wait_group %0;" :: "n"(n) : "memory")

// ---------------------------------------------------------------------------
// Kernel 1: CSR row_ptr scatter (+ kl zero) fused with W fp16 hi/lo split
// ---------------------------------------------------------------------------
__global__ void prep_kernel(const int* __restrict__ row,
                            const float* __restrict__ W, int n, int e) {
    const int i = blockIdx.x * blockDim.x + threadIdx.x;
    if (i == 0) g_kl = 0.0f;
    if (i < UNITS * F_DIM) {      // W split (transposed)
        const int nn = i / F_DIM, kk = i % F_DIM;
        const float w = W[kk * UNITS + nn];
        const __half h = __float2half(w);
        g_Wh[i] = h;
        g_Wl[i] = __float2half(w - __half2float(h));
    }
    if (i > e) return;            // rowptr boundary scatter
    int prev = (i == 0) ? -1 : row[i - 1];
    int cur  = (i == e) ? n  : row[i];
    for (int j = prev + 1; j <= cur; j++) g_rowptr[j] = i;
}

// ---------------------------------------------------------------------------
// Kernel 2: WMMA fp16 2-pass GEMM (D = A*Wh + A*Wl), 3-stage cp.async pipe.
// 256 thr (8 warps), M_TILE=64, 2 CTAs/SM (105KB smem each).
// Warp (rg=wid>>2, cg=wid&3) owns 32 rows x 64 cols.
// ---------------------------------------------------------------------------
__global__ __launch_bounds__(THREADS, 2) void gemm_wmma_kernel(
    const float* __restrict__ feat, int n)
{
    extern __shared__ char smem[];
    __half* Ah = reinterpret_cast<__half*>(smem);        // 64*264*2 = 33792 B
    __half* Bbase = Ah + M_TILE * LDA;                   // 3 bufs x 12288 halfs
    float* C = reinterpret_cast<float*>(smem);           // epilogue reuse

    const int tid = threadIdx.x;
    const int wid = tid >> 5, lane = tid & 31;
    const int row0 = blockIdx.x * M_TILE;
    const int nrows = min(M_TILE, n - row0);

    const int BUF_ELEMS = 2 * 256 * LDB;                 // hi+lo per buffer

    // prefetch B chunks 0 and 1 (2 groups in flight before A staging)
#pragma unroll
    for (int pc = 0; pc < 2; pc++) {
        __half* Bh = Bbase + pc * BUF_ELEMS;
        __half* Bl = Bh + 256 * LDB;
        const int kc = pc * KC;
#pragma unroll
        for (int it = 0; it < 2; it++) {
            const int g = it * THREADS + tid;            // 0..511
            const int nn = g >> 1;                       // 0..255
            const int k8 = (g & 1) << 3;                 // 0 or 8
            const size_t goff = (size_t)nn * F_DIM + kc + k8;
            cp_async16(smem_u32(Bh + nn * LDB + k8), g_Wh + goff);
            cp_async16(smem_u32(Bl + nn * LDB + k8), g_Wl + goff);
        }
        CP_COMMIT();
    }

    // --- stage A: fp32 -> fp16 ---
#pragma unroll
    for (int it = 0; it < 16; it++) {
        const int j = it * THREADS + tid;                // float4 id, 0..4095
        const int r = j >> 6;                            // row 0..63
        const int c4 = (j & 63) << 2;
        float4 v = make_float4(0.f, 0.f, 0.f, 0.f);
        if (r < nrows)
            v = reinterpret_cast<const float4*>(feat + (size_t)(row0 + r) * F_DIM)[j & 63];
        __half2 p0; p0.x = __float2half(v.x); p0.y = __float2half(v.y);
        __half2 p1; p1.x = __float2half(v.z); p1.y = __float2half(v.w);
        reinterpret_cast<__half2*>(Ah + r * LDA + c4)[0] = p0;
        reinterpret_cast<__half2*>(Ah + r * LDA + c4)[1] = p1;
    }

    const int rg = wid >> 2;            // 0..1 (32-row group)
    const int cg = wid & 3;             // 0..3 (64-col group)

    wmma::fragment<wmma::accumulator, 16, 16, 16, float> acc[2][4];
#pragma unroll
    for (int i = 0; i < 2; i++)
#pragma unroll
        for (int j = 0; j < 4; j++) wmma::fill_fragment(acc[i][j], 0.0f);

    // --- 3-stage pipelined mainloop: at iter c, chunk c is guaranteed
    //     landed (wait ≤1 outstanding of {c, c+1}); prefetch c+2. ---
    for (int c = 0; c < NCHUNK; c++) {
        if (c < NCHUNK - 1) { CP_WAIT(1); } else { CP_WAIT(0); }
        __syncthreads();    // chunk c visible to all; buf (c+2)%3 free

        if (c + 2 < NCHUNK) {
            const int b = (c + 2) % NBUF;
            const int kcn = (c + 2) * KC;
            __half* Bh = Bbase + b * BUF_ELEMS;
            __half* Bl = Bh + 256 * LDB;
#pragma unroll
            for (int it = 0; it < 2; it++) {
                const int g = it * THREADS + tid;
                const int nn = g >> 1;
                const int k8 = (g & 1) << 3;
                const size_t goff = (size_t)nn * F_DIM + kcn + k8;
                cp_async16(smem_u32(Bh + nn * LDB + k8), g_Wh + goff);
                cp_async16(smem_u32(Bl + nn * LDB + k8), g_Wl + goff);
            }
            CP_COMMIT();
        }

        const int kc = c * KC;
        const __half* Bh = Bbase + (c % NBUF) * BUF_ELEMS;
        const __half* Bl = Bh + 256 * LDB;

        wmma::fragment<wmma::matrix_a, 16, 16, 16, __half, wmma::row_major> fah[2];
#pragma unroll
        for (int i = 0; i < 2; i++)
            wmma::load_matrix_sync(fah[i], Ah + (rg * 32 + i * 16) * LDA + kc, LDA);
#pragma unroll
        for (int j = 0; j < 4; j++) {
            const int ncol = cg * 64 + j * 16;
            wmma::fragment<wmma::matrix_b, 16, 16, 16, __half, wmma::col_major> fbh, fbl;
            wmma::load_matrix_sync(fbh, Bh + ncol * LDB, LDB);
            wmma::load_matrix_sync(fbl, Bl + ncol * LDB, LDB);
            wmma::mma_sync(acc[0][j], fah[0], fbh, acc[0][j]);
            wmma::mma_sync(acc[1][j], fah[1], fbh, acc[1][j]);
            wmma::mma_sync(acc[0][j], fah[0], fbl, acc[0][j]);
            wmma::mma_sync(acc[1][j], fah[1], fbl, acc[1][j]);
        }
    }
    __syncthreads();   // smem no longer needed as A/B; reuse as C

#pragma unroll
    for (int i = 0; i < 2; i++)
#pragma unroll
        for (int j = 0; j < 4; j++)
            wmma::store_matrix_sync(C + (rg * 32 + i * 16) * LDC + cg * 64 + j * 16,
                                    acc[i][j], LDC, wmma::mem_row_major);
    __syncthreads();

    // --- epilogue: activations, attention, KL; g_x in fp16 ---
    float kl = 0.f;
#pragma unroll
    for (int it = 0; it < 16; it++) {
        const int idx = it * THREADS + tid;              // 0..4095
        const int r = idx >> 6;                          // 0..63
        const int d2 = (idx & 63) << 1;                  // even d, 0..126
        if (r < nrows) {
            float mo[2], vo[2];
#pragma unroll
            for (int q = 0; q < 2; q++) {
                const float hm = C[r * LDC + d2 + q];
                const float hv = C[r * LDC + DIM + d2 + q];
                const float m = elu_f(hm);
                const float v = hv > 0.f ? hv : 0.f;
                const float att = fast_exp(-v);
                kl += m * m + v - logf(1e-8f + v) - 1.f;
                mo[q] = m * att;
                vo[q] = v * att * att;
            }
            const size_t base = (size_t)(row0 + r) * UNITS;
            __half2 hm2; hm2.x = __float2half(mo[0]); hm2.y = __float2half(mo[1]);
            __half2 hv2; hv2.x = __float2half(vo[0]); hv2.y = __float2half(vo[1]);
            *reinterpret_cast<__half2*>(g_xh + base + d2)       = hm2;
            *reinterpret_cast<__half2*>(g_xh + base + DIM + d2) = hv2;
        }
    }
    kl *= 0.5f / (float)DIM;

    __shared__ float kl_red[8];
#pragma unroll
    for (int off = 16; off > 0; off >>= 1)
        kl += __shfl_down_sync(0xFFFFFFFFu, kl, off);
    if (lane == 0) kl_red[wid] = kl;
    __syncthreads();
    if (tid == 0) {
        float s = 0.f;
#pragma unroll
        for (int i = 0; i < 8; i++) s += kl_red[i];
        atomicAdd(&g_kl, s);
    }
}

// ---------------------------------------------------------------------------
// Kernel 3: fused dual SpMM on fp16 table. ONE warp per node:
// lanes 0-15 = mean half (adj1), lanes 16-31 = var half (adj2).
// ---------------------------------------------------------------------------
__global__ void spmm_kernel(
    const int* __restrict__ col,
    const float* __restrict__ a1,
    const float* __restrict__ a2,
    float* __restrict__ out,
    int n, int write_kl)
{
    const int gtid = blockIdx.x * blockDim.x + threadIdx.x;
    if (gtid == 0 && write_kl) out[(size_t)n * UNITS] = g_kl;

    const int node = gtid >> 5;
    const int lane = threadIdx.x & 31;
    if (node >= n) return;

    const int s = g_rowptr[node];
    const int e = g_rowptr[node + 1];
    const float* __restrict__ wa = (lane < 16) ? a1 : a2;

    float acc[8];
#pragma unroll
    for (int q = 0; q < 8; q++) acc[q] = 0.f;

    int i = s;
    for (; i + 3 < e; i += 4) {
        int   c[4];
        float w[4];
        uint4 x[4];
#pragma unroll
        for (int u = 0; u < 4; u++) { c[u] = __ldg(&col[i + u]); w[u] = __ldg(&wa[i + u]); }
#pragma unroll
        for (int u = 0; u < 4; u++)
            x[u] = __ldg(reinterpret_cast<const uint4*>(g_xh + (size_t)c[u] * UNITS) + lane);
#pragma unroll
        for (int u = 0; u < 4; u++) {
            const __half2* hp = reinterpret_cast<const __half2*>(&x[u]);
#pragma unroll
            for (int q = 0; q < 4; q++) {
                const float2 f = __half22float2(hp[q]);
                acc[2 * q]     = fmaf(w[u], f.x, acc[2 * q]);
                acc[2 * q + 1] = fmaf(w[u], f.y, acc[2 * q + 1]);
            }
        }
    }
    for (; i < e; i++) {
        const int c0 = __ldg(&col[i]);
        const float w0 = __ldg(&wa[i]);
        const uint4 x0 = __ldg(reinterpret_cast<const uint4*>(g_xh + (size_t)c0 * UNITS) + lane);
        const __half2* hp = reinterpret_cast<const __half2*>(&x0);
#pragma unroll
        for (int q = 0; q < 4; q++) {
            const float2 f = __half22float2(hp[q]);
            acc[2 * q]     = fmaf(w0, f.x, acc[2 * q]);
            acc[2 * q + 1] = fmaf(w0, f.y, acc[2 * q + 1]);
        }
    }

    float* o = out + (size_t)node * UNITS + lane * 8;
    *reinterpret_cast<float4*>(o)     = make_float4(acc[0], acc[1], acc[2], acc[3]);
    *reinterpret_cast<float4*>(o + 4) = make_float4(acc[4], acc[5], acc[6], acc[7]);
}

// ---------------------------------------------------------------------------
extern "C" void kernel_launch(void* const* d_in, const int* in_sizes, int n_in,
                              void* d_out, int out_size) {
    const float* feat = (const float*)d_in[0];
    const float* W    = (const float*)d_in[1];
    const int*   row  = (const int*)d_in[2];
    const int*   col  = (const int*)d_in[3];
    const float* a1   = (const float*)d_in[4];
    const float* a2   = (const float*)d_in[5];
    float* out = (float*)d_out;

    const int n = in_sizes[0] / F_DIM;
    const int e = in_sizes[2];
    const int write_kl = (out_size > n * UNITS) ? 1 : 0;

    {   // fused prep: rowptr scatter + W split
        const int threads = 256;
        const int work = (e + 1 > UNITS * F_DIM) ? e + 1 : UNITS * F_DIM;
        prep_kernel<<<(work + threads - 1) / threads, threads>>>(row, W, n, e);
    }
    {   // fp16 2-pass WMMA GEMM + epilogue (105KB smem, 2 CTAs/SM)
        const int smem_total = M_TILE * LDA * 2 + NBUF * (2 * 256 * LDB) * 2; // 107520
        cudaFuncSetAttribute(gemm_wmma_kernel,
                             cudaFuncAttributeMaxDynamicSharedMemorySize, smem_total);
        gemm_wmma_kernel<<<(n + M_TILE - 1) / M_TILE, THREADS, smem_total>>>(feat, n);
    }
    {   // dual SpMM, 1 warp per node
        const int threads = 256;
        spmm_kernel<<<(n * 32 + threads - 1) / threads, threads>>>(col, a1, a2, out, n, write_kl);
    }
}

// round 10
// speedup vs baseline: 1.3268x; 1.3268x over previous
#include <cuda_runtime.h>
#include <cuda_fp16.h>
#include <mma.h>
#include <math.h>
#include <stdint.h>

using namespace nvcuda;

// Problem constants: N=100000, F=256, UNITS=256, DIM=128
#define F_DIM   256
#define UNITS   256
#define DIM     128
#define N_MAX   100000
#define M_TILE  64
#define THREADS 256
#define LDA     264          // A smem leading dim (halfs), 528B stride
#define LDB     40           // B smem leading dim (halfs), 80B stride
#define LDC     260          // C smem leading dim (floats), 1040B stride
#define KC      32           // K chunk per pipeline stage
#define NCHUNK  (F_DIM / KC) // 8
#define NBUF    2            // pipeline depth

// Scratch
__device__ __half g_xh[(size_t)N_MAX * UNITS];   // packed [mean|var] fp16, ~51 MB
__device__ int    g_rowptr[N_MAX + 1];
__device__ float  g_kl;
__device__ __half g_Wh[UNITS * F_DIM];           // W^T fp16 (round-to-nearest), [n][k]

// ---------------------------------------------------------------------------
// MUFU-free exp (x <= 0) and elu
// ---------------------------------------------------------------------------
__device__ __forceinline__ float fast_exp(float x) {
    x = fmaxf(x, -80.f);
    const float t = x * 1.4426950408889634f;
    const float nf = rintf(t);
    const float f = t - nf;
    float p = 1.5253232e-5f;
    p = fmaf(p, f, 1.54035304e-4f);
    p = fmaf(p, f, 1.33335581e-3f);
    p = fmaf(p, f, 9.61812911e-3f);
    p = fmaf(p, f, 5.55041087e-2f);
    p = fmaf(p, f, 2.40226507e-1f);
    p = fmaf(p, f, 6.93147181e-1f);
    p = fmaf(p, f, 1.0f);
    return __int_as_float(__float_as_int(p) + (((int)nf) << 23));
}
__device__ __forceinline__ float elu_f(float x) {
    if (x > 0.f) return x;
    if (x > -0.5f) {
        float p = 1.98412698e-4f;
        p = fmaf(p, x, 1.38888889e-3f);
        p = fmaf(p, x, 8.33333333e-3f);
        p = fmaf(p, x, 4.16666667e-2f);
        p = fmaf(p, x, 1.66666667e-1f);
        p = fmaf(p, x, 0.5f);
        p = fmaf(p, x, 1.0f);
        return x * p;
    }
    return fast_exp(x) - 1.0f;
}

__device__ __forceinline__ uint32_t smem_u32(const void* p) {
    uint32_t a;
    asm("{ .reg .u64 t; cvta.to.shared.u64 t, %1; cvt.u32.u64 %0, t; }"
        : "=r"(a) : "l"(p));
    return a;
}
__device__ __forceinline__ void cp_async16(uint32_t dst, const void* src) {
    asm volatile("cp.async.cg.shared.global [%0], [%1], 16;"
                 :: "r"(dst), "l"(src) : "memory");
}
#define CP_COMMIT()  asm volatile("cp.async.commit_group;" ::: "memory")
#define CP_WAIT(n)   asm volatile("cp.async.wait_group %0;" :: "n"(n) : "memory")

// ---------------------------------------------------------------------------
// Kernel 1: CSR row_ptr scatter (+ kl zero) fused with W fp16 transpose
// ---------------------------------------------------------------------------
__global__ void prep_kernel(const int* __restrict__ row,
                            const float* __restrict__ W, int n, int e) {
    const int i = blockIdx.x * blockDim.x + threadIdx.x;
    if (i == 0) g_kl = 0.0f;
    if (i < UNITS * F_DIM) {      // W transpose + fp16 round
        const int nn = i / F_DIM, kk = i % F_DIM;
        g_Wh[i] = __float2half(W[kk * UNITS + nn]);
    }
    if (i > e) return;            // rowptr boundary scatter
    int prev = (i == 0) ? -1 : row[i - 1];
    int cur  = (i == e) ? n  : row[i];
    for (int j = prev + 1; j <= cur; j++) g_rowptr[j] = i;
}

// ---------------------------------------------------------------------------
// Kernel 2: single-pass fp16 WMMA GEMM, double-buffered cp.async.
// 256 thr (8 warps), M_TILE=64, 2 CTAs/SM (74KB smem each).
// Warp (rg=wid>>2, cg=wid&3) owns 32 rows x 64 cols.
// ---------------------------------------------------------------------------
__global__ __launch_bounds__(THREADS, 2) void gemm_wmma_kernel(
    const float* __restrict__ feat, int n)
{
    extern __shared__ char smem[];
    __half* Ah = reinterpret_cast<__half*>(smem);        // 64*264*2 = 33792 B
    __half* Bbase = Ah + M_TILE * LDA;                   // 2 bufs x 10240 halfs
    float* C = reinterpret_cast<float*>(smem);           // epilogue reuse

    const int tid = threadIdx.x;
    const int wid = tid >> 5, lane = tid & 31;
    const int row0 = blockIdx.x * M_TILE;
    const int nrows = min(M_TILE, n - row0);

    const int BUF_ELEMS = 256 * LDB;

    // prefetch B chunk 0
    {
        __half* Bh = Bbase;
#pragma unroll
        for (int it = 0; it < 4; it++) {
            const int g = it * THREADS + tid;            // 0..1023
            const int nn = g >> 2;                       // 0..255
            const int k8 = (g & 3) << 3;                 // 0,8,16,24
            cp_async16(smem_u32(Bh + nn * LDB + k8), g_Wh + (size_t)nn * F_DIM + k8);
        }
        CP_COMMIT();
    }

    // --- stage A: fp32 -> fp16 ---
#pragma unroll
    for (int it = 0; it < 16; it++) {
        const int j = it * THREADS + tid;                // float4 id, 0..4095
        const int r = j >> 6;                            // row 0..63
        const int c4 = (j & 63) << 2;
        float4 v = make_float4(0.f, 0.f, 0.f, 0.f);
        if (r < nrows)
            v = reinterpret_cast<const float4*>(feat + (size_t)(row0 + r) * F_DIM)[j & 63];
        __half2 p0; p0.x = __float2half(v.x); p0.y = __float2half(v.y);
        __half2 p1; p1.x = __float2half(v.z); p1.y = __float2half(v.w);
        reinterpret_cast<__half2*>(Ah + r * LDA + c4)[0] = p0;
        reinterpret_cast<__half2*>(Ah + r * LDA + c4)[1] = p1;
    }

    const int rg = wid >> 2;            // 0..1 (32-row group)
    const int cg = wid & 3;             // 0..3 (64-col group)

    wmma::fragment<wmma::accumulator, 16, 16, 16, float> acc[2][4];
#pragma unroll
    for (int i = 0; i < 2; i++)
#pragma unroll
        for (int j = 0; j < 4; j++) wmma::fill_fragment(acc[i][j], 0.0f);

    CP_WAIT(0);
    __syncthreads();

    // --- double-buffered mainloop over 8 K-chunks of 32 ---
    for (int c = 0; c < NCHUNK; c++) {
        const int kc = c * KC;
        if (c < NCHUNK - 1) {            // prefetch chunk c+1
            __half* Bh = Bbase + ((c + 1) & 1) * BUF_ELEMS;
            const int kcn = kc + KC;
#pragma unroll
            for (int it = 0; it < 4; it++) {
                const int g = it * THREADS + tid;
                const int nn = g >> 2;
                const int k8 = (g & 3) << 3;
                cp_async16(smem_u32(Bh + nn * LDB + k8),
                           g_Wh + (size_t)nn * F_DIM + kcn + k8);
            }
            CP_COMMIT();
        }

        const __half* Bh = Bbase + (c & 1) * BUF_ELEMS;
#pragma unroll
        for (int ks = 0; ks < KC; ks += 16) {
            wmma::fragment<wmma::matrix_a, 16, 16, 16, __half, wmma::row_major> fah[2];
#pragma unroll
            for (int i = 0; i < 2; i++)
                wmma::load_matrix_sync(fah[i], Ah + (rg * 32 + i * 16) * LDA + kc + ks, LDA);
#pragma unroll
            for (int j = 0; j < 4; j++) {
                const int ncol = cg * 64 + j * 16;
                wmma::fragment<wmma::matrix_b, 16, 16, 16, __half, wmma::col_major> fbh;
                wmma::load_matrix_sync(fbh, Bh + ncol * LDB + ks, LDB);
                wmma::mma_sync(acc[0][j], fah[0], fbh, acc[0][j]);
                wmma::mma_sync(acc[1][j], fah[1], fbh, acc[1][j]);
            }
        }

        if (c < NCHUNK - 1) {
            CP_WAIT(0);
            __syncthreads();
        }
    }
    __syncthreads();   // smem no longer needed as A/B; reuse as C

#pragma unroll
    for (int i = 0; i < 2; i++)
#pragma unroll
        for (int j = 0; j < 4; j++)
            wmma::store_matrix_sync(C + (rg * 32 + i * 16) * LDC + cg * 64 + j * 16,
                                    acc[i][j], LDC, wmma::mem_row_major);
    __syncthreads();

    // --- epilogue: activations, attention, KL; g_x in fp16 ---
    float kl = 0.f;
#pragma unroll
    for (int it = 0; it < 16; it++) {
        const int idx = it * THREADS + tid;              // 0..4095
        const int r = idx >> 6;                          // 0..63
        const int d2 = (idx & 63) << 1;                  // even d, 0..126
        if (r < nrows) {
            float mo[2], vo[2];
#pragma unroll
            for (int q = 0; q < 2; q++) {
                const float hm = C[r * LDC + d2 + q];
                const float hv = C[r * LDC + DIM + d2 + q];
                const float m = elu_f(hm);
                const float v = hv > 0.f ? hv : 0.f;
                const float att = fast_exp(-v);
                kl += m * m + v - logf(1e-8f + v) - 1.f;
                mo[q] = m * att;
                vo[q] = v * att * att;
            }
            const size_t base = (size_t)(row0 + r) * UNITS;
            __half2 hm2; hm2.x = __float2half(mo[0]); hm2.y = __float2half(mo[1]);
            __half2 hv2; hv2.x = __float2half(vo[0]); hv2.y = __float2half(vo[1]);
            *reinterpret_cast<__half2*>(g_xh + base + d2)       = hm2;
            *reinterpret_cast<__half2*>(g_xh + base + DIM + d2) = hv2;
        }
    }
    kl *= 0.5f / (float)DIM;

    __shared__ float kl_red[8];
#pragma unroll
    for (int off = 16; off > 0; off >>= 1)
        kl += __shfl_down_sync(0xFFFFFFFFu, kl, off);
    if (lane == 0) kl_red[wid] = kl;
    __syncthreads();
    if (tid == 0) {
        float s = 0.f;
#pragma unroll
        for (int i = 0; i < 8; i++) s += kl_red[i];
        atomicAdd(&g_kl, s);
    }
}

// ---------------------------------------------------------------------------
// Kernel 3: fused dual SpMM on fp16 table. ONE warp per node:
// lanes 0-15 = mean half (adj1), lanes 16-31 = var half (adj2).
// ---------------------------------------------------------------------------
__global__ void spmm_kernel(
    const int* __restrict__ col,
    const float* __restrict__ a1,
    const float* __restrict__ a2,
    float* __restrict__ out,
    int n, int write_kl)
{
    const int gtid = blockIdx.x * blockDim.x + threadIdx.x;
    if (gtid == 0 && write_kl) out[(size_t)n * UNITS] = g_kl;

    const int node = gtid >> 5;
    const int lane = threadIdx.x & 31;
    if (node >= n) return;

    const int s = g_rowptr[node];
    const int e = g_rowptr[node + 1];
    const float* __restrict__ wa = (lane < 16) ? a1 : a2;

    float acc[8];
#pragma unroll
    for (int q = 0; q < 8; q++) acc[q] = 0.f;

    int i = s;
    for (; i + 3 < e; i += 4) {
        int   c[4];
        float w[4];
        uint4 x[4];
#pragma unroll
        for (int u = 0; u < 4; u++) { c[u] = __ldg(&col[i + u]); w[u] = __ldg(&wa[i + u]); }
#pragma unroll
        for (int u = 0; u < 4; u++)
            x[u] = __ldg(reinterpret_cast<const uint4*>(g_xh + (size_t)c[u] * UNITS) + lane);
#pragma unroll
        for (int u = 0; u < 4; u++) {
            const __half2* hp = reinterpret_cast<const __half2*>(&x[u]);
#pragma unroll
            for (int q = 0; q < 4; q++) {
                const float2 f = __half22float2(hp[q]);
                acc[2 * q]     = fmaf(w[u], f.x, acc[2 * q]);
                acc[2 * q + 1] = fmaf(w[u], f.y, acc[2 * q + 1]);
            }
        }
    }
    for (; i < e; i++) {
        const int c0 = __ldg(&col[i]);
        const float w0 = __ldg(&wa[i]);
        const uint4 x0 = __ldg(reinterpret_cast<const uint4*>(g_xh + (size_t)c0 * UNITS) + lane);
        const __half2* hp = reinterpret_cast<const __half2*>(&x0);
#pragma unroll
        for (int q = 0; q < 4; q++) {
            const float2 f = __half22float2(hp[q]);
            acc[2 * q]     = fmaf(w0, f.x, acc[2 * q]);
            acc[2 * q + 1] = fmaf(w0, f.y, acc[2 * q + 1]);
        }
    }

    float* o = out + (size_t)node * UNITS + lane * 8;
    *reinterpret_cast<float4*>(o)     = make_float4(acc[0], acc[1], acc[2], acc[3]);
    *reinterpret_cast<float4*>(o + 4) = make_float4(acc[4], acc[5], acc[6], acc[7]);
}

// ---------------------------------------------------------------------------
extern "C" void kernel_launch(void* const* d_in, const int* in_sizes, int n_in,
                              void* d_out, int out_size) {
    const float* feat = (const float*)d_in[0];
    const float* W    = (const float*)d_in[1];
    const int*   row  = (const int*)d_in[2];
    const int*   col  = (const int*)d_in[3];
    const float* a1   = (const float*)d_in[4];
    const float* a2   = (const float*)d_in[5];
    float* out = (float*)d_out;

    const int n = in_sizes[0] / F_DIM;
    const int e = in_sizes[2];
    const int write_kl = (out_size > n * UNITS) ? 1 : 0;

    {   // fused prep: rowptr scatter + W transpose/round
        const int threads = 256;
        const int work = (e + 1 > UNITS * F_DIM) ? e + 1 : UNITS * F_DIM;
        prep_kernel<<<(work + threads - 1) / threads, threads>>>(row, W, n, e);
    }
    {   // single-pass fp16 WMMA GEMM + epilogue (74KB smem, 2 CTAs/SM)
        const int smem_total = M_TILE * LDA * 2 + NBUF * (256 * LDB) * 2; // 74752
        cudaFuncSetAttribute(gemm_wmma_kernel,
                             cudaFuncAttributeMaxDynamicSharedMemorySize, smem_total);
        gemm_wmma_kernel<<<(n + M_TILE - 1) / M_TILE, THREADS, smem_total>>>(feat, n);
    }
    {   // dual SpMM, 1 warp per node
        const int threads = 256;
        spmm_kernel<<<(n * 32 + threads - 1) / threads, threads>>>(col, a1, a2, out, n, write_kl);
    }
}

// round 11
// speedup vs baseline: 1.5669x; 1.1810x over previous
#include <cuda_runtime.h>
#include <cuda_fp16.h>
#include <mma.h>
#include <math.h>
#include <stdint.h>

using namespace nvcuda;

// Problem constants: N=100000, F=256, UNITS=256, DIM=128
#define F_DIM   256
#define UNITS   256
#define DIM     128
#define N_MAX   100000
#define M_TILE  64
#define THREADS 256
#define LDA     264          // A smem leading dim (halfs), 528B stride
#define LDB     72           // B smem leading dim (halfs), 144B stride
#define LDC     260          // C smem leading dim (floats), 1040B stride
#define KC      64           // K chunk per pipeline stage
#define NCHUNK  (F_DIM / KC) // 4
#define NBUF    2            // pipeline depth

// Scratch
__device__ __half g_xh[(size_t)N_MAX * UNITS];   // packed [mean|var] fp16, ~51 MB
__device__ int    g_rowptr[N_MAX + 1];
__device__ float  g_kl;
__device__ __half g_Wh[UNITS * F_DIM];           // W^T fp16, [n][k]

__device__ __forceinline__ uint32_t smem_u32(const void* p) {
    uint32_t a;
    asm("{ .reg .u64 t; cvta.to.shared.u64 t, %1; cvt.u32.u64 %0, t; }"
        : "=r"(a) : "l"(p));
    return a;
}
__device__ __forceinline__ void cp_async16(uint32_t dst, const void* src) {
    asm volatile("cp.async.cg.shared.global [%0], [%1], 16;"
                 :: "r"(dst), "l"(src) : "memory");
}
#define CP_COMMIT()  asm volatile("cp.async.commit_group;" ::: "memory")
#define CP_WAIT(n)   asm volatile("cp.async.wait_group %0;" :: "n"(n) : "memory")

// ---------------------------------------------------------------------------
// Kernel 1: CSR row_ptr scatter (+ kl zero) fused with W fp16 transpose
// ---------------------------------------------------------------------------
__global__ void prep_kernel(const int* __restrict__ row,
                            const float* __restrict__ W, int n, int e) {
    const int i = blockIdx.x * blockDim.x + threadIdx.x;
    if (i == 0) g_kl = 0.0f;
    if (i < UNITS * F_DIM) {      // W transpose + fp16 round
        const int nn = i / F_DIM, kk = i % F_DIM;
        g_Wh[i] = __float2half(W[kk * UNITS + nn]);
    }
    if (i > e) return;            // rowptr boundary scatter
    int prev = (i == 0) ? -1 : row[i - 1];
    int cur  = (i == e) ? n  : row[i];
    for (int j = prev + 1; j <= cur; j++) g_rowptr[j] = i;
}

// ---------------------------------------------------------------------------
// Kernel 2: single-pass fp16 WMMA GEMM, double-buffered cp.async, KC=64.
// 256 thr (8 warps), M_TILE=64, 2 CTAs/SM (107.5KB smem each).
// Warp (rg=wid>>2, cg=wid&3) owns 32 rows x 64 cols.
// Epilogue uses MUFU (__expf/__logf) to stay off the FMA pipe.
// ---------------------------------------------------------------------------
__global__ __launch_bounds__(THREADS, 2) void gemm_wmma_kernel(
    const float* __restrict__ feat, int n)
{
    extern __shared__ char smem[];
    __half* Ah = reinterpret_cast<__half*>(smem);        // 64*264*2 = 33792 B
    __half* Bbase = Ah + M_TILE * LDA;                   // 2 bufs x 18432 halfs
    float* C = reinterpret_cast<float*>(smem);           // epilogue reuse

    const int tid = threadIdx.x;
    const int wid = tid >> 5, lane = tid & 31;
    const int row0 = blockIdx.x * M_TILE;
    const int nrows = min(M_TILE, n - row0);

    const int BUF_ELEMS = 256 * LDB;

    // prefetch B chunk 0 (256 n-rows x 64 k)
    {
        __half* Bh = Bbase;
#pragma unroll
        for (int it = 0; it < 8; it++) {
            const int g = it * THREADS + tid;            // 0..2047
            const int nn = g >> 3;                       // 0..255
            const int k8 = (g & 7) << 3;                 // 0..56
            cp_async16(smem_u32(Bh + nn * LDB + k8), g_Wh + (size_t)nn * F_DIM + k8);
        }
        CP_COMMIT();
    }

    // --- stage A: fp32 -> fp16 ---
#pragma unroll
    for (int it = 0; it < 16; it++) {
        const int j = it * THREADS + tid;                // float4 id, 0..4095
        const int r = j >> 6;                            // row 0..63
        const int c4 = (j & 63) << 2;
        float4 v = make_float4(0.f, 0.f, 0.f, 0.f);
        if (r < nrows)
            v = reinterpret_cast<const float4*>(feat + (size_t)(row0 + r) * F_DIM)[j & 63];
        __half2 p0; p0.x = __float2half(v.x); p0.y = __float2half(v.y);
        __half2 p1; p1.x = __float2half(v.z); p1.y = __float2half(v.w);
        reinterpret_cast<__half2*>(Ah + r * LDA + c4)[0] = p0;
        reinterpret_cast<__half2*>(Ah + r * LDA + c4)[1] = p1;
    }

    const int rg = wid >> 2;            // 0..1 (32-row group)
    const int cg = wid & 3;             // 0..3 (64-col group)

    wmma::fragment<wmma::accumulator, 16, 16, 16, float> acc[2][4];
#pragma unroll
    for (int i = 0; i < 2; i++)
#pragma unroll
        for (int j = 0; j < 4; j++) wmma::fill_fragment(acc[i][j], 0.0f);

    CP_WAIT(0);
    __syncthreads();

    // --- double-buffered mainloop over 4 K-chunks of 64 ---
    for (int c = 0; c < NCHUNK; c++) {
        const int kc = c * KC;
        if (c < NCHUNK - 1) {            // prefetch chunk c+1
            __half* Bh = Bbase + ((c + 1) & 1) * BUF_ELEMS;
            const int kcn = kc + KC;
#pragma unroll
            for (int it = 0; it < 8; it++) {
                const int g = it * THREADS + tid;
                const int nn = g >> 3;
                const int k8 = (g & 7) << 3;
                cp_async16(smem_u32(Bh + nn * LDB + k8),
                           g_Wh + (size_t)nn * F_DIM + kcn + k8);
            }
            CP_COMMIT();
        }

        const __half* Bh = Bbase + (c & 1) * BUF_ELEMS;
#pragma unroll
        for (int ks = 0; ks < KC; ks += 16) {
            wmma::fragment<wmma::matrix_a, 16, 16, 16, __half, wmma::row_major> fah[2];
#pragma unroll
            for (int i = 0; i < 2; i++)
                wmma::load_matrix_sync(fah[i], Ah + (rg * 32 + i * 16) * LDA + kc + ks, LDA);
#pragma unroll
            for (int j = 0; j < 4; j++) {
                const int ncol = cg * 64 + j * 16;
                wmma::fragment<wmma::matrix_b, 16, 16, 16, __half, wmma::col_major> fbh;
                wmma::load_matrix_sync(fbh, Bh + ncol * LDB + ks, LDB);
                wmma::mma_sync(acc[0][j], fah[0], fbh, acc[0][j]);
                wmma::mma_sync(acc[1][j], fah[1], fbh, acc[1][j]);
            }
        }

        if (c < NCHUNK - 1) {
            CP_WAIT(0);
            __syncthreads();
        }
    }
    __syncthreads();   // smem no longer needed as A/B; reuse as C

#pragma unroll
    for (int i = 0; i < 2; i++)
#pragma unroll
        for (int j = 0; j < 4; j++)
            wmma::store_matrix_sync(C + (rg * 32 + i * 16) * LDC + cg * 64 + j * 16,
                                    acc[i][j], LDC, wmma::mem_row_major);
    __syncthreads();

    // --- epilogue: activations via MUFU, KL; g_x in fp16 ---
    float kl = 0.f;
#pragma unroll
    for (int it = 0; it < 16; it++) {
        const int idx = it * THREADS + tid;              // 0..4095
        const int r = idx >> 6;                          // 0..63
        const int d2 = (idx & 63) << 1;                  // even d, 0..126
        if (r < nrows) {
            float mo[2], vo[2];
#pragma unroll
            for (int q = 0; q < 2; q++) {
                const float hm = C[r * LDC + d2 + q];
                const float hv = C[r * LDC + DIM + d2 + q];
                const float m = hm > 0.f ? hm : (__expf(hm) - 1.0f);
                const float v = hv > 0.f ? hv : 0.f;
                const float att = __expf(-v);
                kl += m * m + v - __logf(1e-8f + v) - 1.f;
                mo[q] = m * att;
                vo[q] = v * att * att;
            }
            const size_t base = (size_t)(row0 + r) * UNITS;
            __half2 hm2; hm2.x = __float2half(mo[0]); hm2.y = __float2half(mo[1]);
            __half2 hv2; hv2.x = __float2half(vo[0]); hv2.y = __float2half(vo[1]);
            *reinterpret_cast<__half2*>(g_xh + base + d2)       = hm2;
            *reinterpret_cast<__half2*>(g_xh + base + DIM + d2) = hv2;
        }
    }
    kl *= 0.5f / (float)DIM;

    __shared__ float kl_red[8];
#pragma unroll
    for (int off = 16; off > 0; off >>= 1)
        kl += __shfl_down_sync(0xFFFFFFFFu, kl, off);
    if (lane == 0) kl_red[wid] = kl;
    __syncthreads();
    if (tid == 0) {
        float s = 0.f;
#pragma unroll
        for (int i = 0; i < 8; i++) s += kl_red[i];
        atomicAdd(&g_kl, s);
    }
}

// ---------------------------------------------------------------------------
// Kernel 3: fused dual SpMM on fp16 table. ONE warp per node:
// lanes 0-15 = mean half (adj1), lanes 16-31 = var half (adj2).
// ---------------------------------------------------------------------------
__global__ void spmm_kernel(
    const int* __restrict__ col,
    const float* __restrict__ a1,
    const float* __restrict__ a2,
    float* __restrict__ out,
    int n, int write_kl)
{
    const int gtid = blockIdx.x * blockDim.x + threadIdx.x;
    if (gtid == 0 && write_kl) out[(size_t)n * UNITS] = g_kl;

    const int node = gtid >> 5;
    const int lane = threadIdx.x & 31;
    if (node >= n) return;

    const int s = g_rowptr[node];
    const int e = g_rowptr[node + 1];
    const float* __restrict__ wa = (lane < 16) ? a1 : a2;

    float acc[8];
#pragma unroll
    for (int q = 0; q < 8; q++) acc[q] = 0.f;

    int i = s;
    for (; i + 3 < e; i += 4) {
        int   c[4];
        float w[4];
        uint4 x[4];
#pragma unroll
        for (int u = 0; u < 4; u++) { c[u] = __ldg(&col[i + u]); w[u] = __ldg(&wa[i + u]); }
#pragma unroll
        for (int u = 0; u < 4; u++)
            x[u] = __ldg(reinterpret_cast<const uint4*>(g_xh + (size_t)c[u] * UNITS) + lane);
#pragma unroll
        for (int u = 0; u < 4; u++) {
            const __half2* hp = reinterpret_cast<const __half2*>(&x[u]);
#pragma unroll
            for (int q = 0; q < 4; q++) {
                const float2 f = __half22float2(hp[q]);
                acc[2 * q]     = fmaf(w[u], f.x, acc[2 * q]);
                acc[2 * q + 1] = fmaf(w[u], f.y, acc[2 * q + 1]);
            }
        }
    }
    for (; i < e; i++) {
        const int c0 = __ldg(&col[i]);
        const float w0 = __ldg(&wa[i]);
        const uint4 x0 = __ldg(reinterpret_cast<const uint4*>(g_xh + (size_t)c0 * UNITS) + lane);
        const __half2* hp = reinterpret_cast<const __half2*>(&x0);
#pragma unroll
        for (int q = 0; q < 4; q++) {
            const float2 f = __half22float2(hp[q]);
            acc[2 * q]     = fmaf(w0, f.x, acc[2 * q]);
            acc[2 * q + 1] = fmaf(w0, f.y, acc[2 * q + 1]);
        }
    }

    float* o = out + (size_t)node * UNITS + lane * 8;
    *reinterpret_cast<float4*>(o)     = make_float4(acc[0], acc[1], acc[2], acc[3]);
    *reinterpret_cast<float4*>(o + 4) = make_float4(acc[4], acc[5], acc[6], acc[7]);
}

// ---------------------------------------------------------------------------
extern "C" void kernel_launch(void* const* d_in, const int* in_sizes, int n_in,
                              void* d_out, int out_size) {
    const float* feat = (const float*)d_in[0];
    const float* W    = (const float*)d_in[1];
    const int*   row  = (const int*)d_in[2];
    const int*   col  = (const int*)d_in[3];
    const float* a1   = (const float*)d_in[4];
    const float* a2   = (const float*)d_in[5];
    float* out = (float*)d_out;

    const int n = in_sizes[0] / F_DIM;
    const int e = in_sizes[2];
    const int write_kl = (out_size > n * UNITS) ? 1 : 0;

    {   // fused prep: rowptr scatter + W transpose/round
        const int threads = 256;
        const int work = (e + 1 > UNITS * F_DIM) ? e + 1 : UNITS * F_DIM;
        prep_kernel<<<(work + threads - 1) / threads, threads>>>(row, W, n, e);
    }
    {   // single-pass fp16 WMMA GEMM + epilogue (107.5KB smem, 2 CTAs/SM)
        const int smem_total = M_TILE * LDA * 2 + NBUF * (256 * LDB) * 2; // 107520
        cudaFuncSetAttribute(gemm_wmma_kernel,
                             cudaFuncAttributeMaxDynamicSharedMemorySize, smem_total);
        gemm_wmma_kernel<<<(n + M_TILE - 1) / M_TILE, THREADS, smem_total>>>(feat, n);
    }
    {   // dual SpMM, 1 warp per node
        const int threads = 256;
        spmm_kernel<<<(n * 32 + threads - 1) / threads, threads>>>(col, a1, a2, out, n, write_kl);
    }
}